// round 3
// baseline (speedup 1.0000x reference)
#include <cuda_runtime.h>

#define HH 192
#define WW 192
#define HWSZ (192*192)
#define CC 64
#define KTAPS 49
#define PADK 3

#define FMA2(d,a,b,c) asm("fma.rn.f32x2 %0, %1, %2, %3;" : "=l"(d) : "l"(a), "l"(b), "l"(c))

typedef unsigned long long ull;

__device__ __forceinline__ ull packpair(float v) {
    unsigned int u = __float_as_uint(v);
    return ((ull)u << 32) | u;
}

// ---------------- scratch (no allocs allowed) ----------------
__device__ float g_rev [CC*HWSZ];
__device__ float g_epre[CC*HWSZ];
__device__ float g_encT[HWSZ*CC];        // NHWC
__device__ ull   g_weff2[KTAPS*64*64];   // [k][c][o] replicated pairs
__device__ ull   g_wc2t2[9*64*64];       // [k][c][o] pairs
__device__ ull   g_wpot2[2*64*128];      // [s][c][o128] pairs
__device__ ull   g_wpit2[64*64];         // [j][c] pairs
__device__ float g_gg  [64*64];          // [c][a*8+d]

// ---------------- precompute: FFT filter -> circular conv kernel ----------------
__global__ void k_prep_g(const float* __restrict__ fw) {
    int c = blockIdx.x;           // 64
    int t = threadIdx.x;          // 64 : a*8+d
    int a = t >> 3, d = t & 7;
    const float ct[8] = {1.f, 0.70710678118654752f, 0.f, -0.70710678118654752f,
                        -1.f, -0.70710678118654752f, 0.f, 0.70710678118654752f};
    const float st[8] = {0.f, 0.70710678118654752f, 1.f, 0.70710678118654752f,
                         0.f, -0.70710678118654752f, -1.f, -0.70710678118654752f};
    const float* w = fw + c * 40; // [8][5]
    float re = 0.f;
    for (int u = 0; u < 8; u++) {
        float rp = w[u*5+0] + ((d & 1) ? -w[u*5+4] : w[u*5+4]);
        float ip = 0.f;
        #pragma unroll
        for (int v = 1; v <= 3; v++) {
            int vd = (v * d) & 7;
            rp += 2.f * w[u*5+v] * ct[vd];
            ip += 2.f * w[u*5+v] * st[vd];
        }
        int ua = (u * a) & 7;
        re += ct[ua] * rp - st[ua] * ip;
    }
    g_gg[c*64 + t] = re * (1.f/64.f);
}

// ---------------- precompute: fused deform weight, replicated pairs ----------------
__global__ void k_prep_weff(const float* __restrict__ wc1, const float* __restrict__ wd) {
    int idx = blockIdx.x * blockDim.x + threadIdx.x;   // k*4096 + c*64 + o
    if (idx >= KTAPS*64*64) return;
    int o = idx & 63, c = (idx >> 6) & 63, k = idx >> 12;
    float s = 0.f;
    for (int m = 0; m < 64; m++)
        s += wc1[o*64 + m] * wd[(m*64 + c)*49 + k];
    g_weff2[idx] = packpair(s);
}

// ---------------- precompute: weight transposes (pairs) ----------------
__global__ void k_prep_tr(const float* __restrict__ wc2, const float* __restrict__ wpo,
                          const float* __restrict__ wpi) {
    int idx = blockIdx.x * blockDim.x + threadIdx.x;
    if (idx < 9*4096) {                       // [k][c][o] <- wc2[o][c][k]
        int o = idx & 63, c = (idx >> 6) & 63, k = idx >> 12;
        g_wc2t2[idx] = packpair(wc2[(o*64 + c)*9 + k]);
    }
    if (idx < 2*8192) {                       // [s][c][o128] <- wpo[o128][s*64+c]
        int s = idx >> 13, c = (idx >> 7) & 63, o = idx & 127;
        g_wpot2[idx] = packpair(wpo[o*128 + s*64 + c]);
    }
    if (idx < 4096) {                         // [j][c] <- wpi[c][j]
        int j = idx >> 6, c = idx & 63;
        g_wpit2[idx] = packpair(wpi[c*64 + j]);
    }
}

// ---------------- NCHW -> NHWC transpose of enc ----------------
__global__ void __launch_bounds__(256) k_transpose(const float* __restrict__ enc) {
    __shared__ float S[64][65];
    int tid = threadIdx.x;
    int p0 = blockIdx.x * 64;
    #pragma unroll
    for (int i = 0; i < 16; i++) {
        int e = i*256 + tid;
        int c = e >> 6, lp = e & 63;
        S[c][lp] = enc[c*HWSZ + p0 + lp];
    }
    __syncthreads();
    #pragma unroll
    for (int i = 0; i < 16; i++) {
        int e = i*256 + tid;           // e = lp*64 + c
        g_encT[p0*64 + e] = S[e & 63][e >> 6];
    }
}

// ---------------- deform conv (+ fused 1x1) : implicit GEMM, 16x16 tile ----------------
#define DEF_SMEM (66560 + 32768 + 4096 + 4096)

__global__ void __launch_bounds__(256, 1) k_deform(const float* __restrict__ off,
                                                   const float* __restrict__ msk) {
    extern __shared__ char dsm[];
    float* Vsh = (float*)dsm;
    ull*   Wsh2 = (ull*)(dsm + 66560);
    int*   sIdx = (int*)(dsm + 66560 + 32768);
    float* sWt  = (float*)(dsm + 66560 + 32768 + 4096);
    const float* encT = g_encT;

    int tid = threadIdx.x;
    int lane = tid & 31;
    int ot = (tid >> 5) * 8;           // warp-uniform o block
    int ph = blockIdx.y * 16, pw = blockIdx.x * 16;
    int ly = tid >> 4, lx = tid & 15;
    int h = ph + ly, w = pw + lx;
    int sp = h * WW + w;

    ull acc[8][4];
    #pragma unroll
    for (int o = 0; o < 8; o++)
        #pragma unroll
        for (int pr = 0; pr < 4; pr++) acc[o][pr] = 0ull;

    for (int k = 0; k < KTAPS; k++) {
        {
            const ulonglong2* wsrc = (const ulonglong2*)(g_weff2 + k*4096);
            ulonglong2* wdst = (ulonglong2*)Wsh2;
            #pragma unroll
            for (int i = 0; i < 8; i++) wdst[tid + i*256] = wsrc[tid + i*256];
        }
        {
            float dy = off[(2*k)*HWSZ + sp];
            float dx = off[(2*k+1)*HWSZ + sp];
            float m  = msk[k*HWSZ + sp];
            float yy = (float)(h - PADK + k/7) + dy;
            float xx = (float)(w - PADK + k%7) + dx;
            float y0f = floorf(yy), x0f = floorf(xx);
            float wy = yy - y0f, wx = xx - x0f;
            int y0 = (int)y0f, x0 = (int)x0f;
            int y1 = y0 + 1,   x1 = x0 + 1;
            bool vy0 = (y0 >= 0) && (y0 < HH), vy1 = (y1 >= 0) && (y1 < HH);
            bool vx0 = (x0 >= 0) && (x0 < WW), vx1 = (x1 >= 0) && (x1 < WW);
            int y0c = min(max(y0, 0), HH-1), y1c = min(max(y1, 0), HH-1);
            int x0c = min(max(x0, 0), WW-1), x1c = min(max(x1, 0), WW-1);
            sIdx[0*256 + tid] = (y0c*WW + x0c) * 64;
            sIdx[1*256 + tid] = (y0c*WW + x1c) * 64;
            sIdx[2*256 + tid] = (y1c*WW + x0c) * 64;
            sIdx[3*256 + tid] = (y1c*WW + x1c) * 64;
            sWt[0*256 + tid] = (vy0 && vx0) ? (1.f-wy)*(1.f-wx)*m : 0.f;
            sWt[1*256 + tid] = (vy0 && vx1) ? (1.f-wy)*wx*m       : 0.f;
            sWt[2*256 + tid] = (vy1 && vx0) ? wy*(1.f-wx)*m       : 0.f;
            sWt[3*256 + tid] = (vy1 && vx1) ? wy*wx*m             : 0.f;
        }
        __syncthreads();

        int c4 = tid & 15;
        #pragma unroll
        for (int it = 0; it < 4; it++) {
            int pq = (tid >> 4) + it * 16;
            int p0 = pq * 4;
            float4 r[4];
            #pragma unroll
            for (int pp = 0; pp < 4; pp++) {
                int p = p0 + pp;
                const float4 t0 = *(const float4*)(encT + sIdx[0*256 + p] + (c4 << 2));
                const float4 t1 = *(const float4*)(encT + sIdx[1*256 + p] + (c4 << 2));
                const float4 t2 = *(const float4*)(encT + sIdx[2*256 + p] + (c4 << 2));
                const float4 t3 = *(const float4*)(encT + sIdx[3*256 + p] + (c4 << 2));
                float w0 = sWt[0*256 + p], w1 = sWt[1*256 + p];
                float w2 = sWt[2*256 + p], w3 = sWt[3*256 + p];
                r[pp].x = w0*t0.x + w1*t1.x + w2*t2.x + w3*t3.x;
                r[pp].y = w0*t0.y + w1*t1.y + w2*t2.y + w3*t3.y;
                r[pp].z = w0*t0.z + w1*t1.z + w2*t2.z + w3*t3.z;
                r[pp].w = w0*t0.w + w1*t1.w + w2*t2.w + w3*t3.w;
            }
            float4 o0 = make_float4(r[0].x, r[1].x, r[2].x, r[3].x);
            float4 o1 = make_float4(r[0].y, r[1].y, r[2].y, r[3].y);
            float4 o2 = make_float4(r[0].z, r[1].z, r[2].z, r[3].z);
            float4 o3 = make_float4(r[0].w, r[1].w, r[2].w, r[3].w);
            *(float4*)&Vsh[(c4*4 + 0)*260 + p0] = o0;
            *(float4*)&Vsh[(c4*4 + 1)*260 + p0] = o1;
            *(float4*)&Vsh[(c4*4 + 2)*260 + p0] = o2;
            *(float4*)&Vsh[(c4*4 + 3)*260 + p0] = o3;
        }
        __syncthreads();

        #pragma unroll 8
        for (int c = 0; c < 64; c++) {
            union { float4 f; ull u[2]; } A, B;
            A.f = *(const float4*)&Vsh[c*260 + 4*lane];
            B.f = *(const float4*)&Vsh[c*260 + 128 + 4*lane];
            const ulonglong2* wp = (const ulonglong2*)(Wsh2 + c*64 + ot);
            ulonglong2 w01 = wp[0], w23 = wp[1], w45 = wp[2], w67 = wp[3];
            ull wv[8] = {w01.x, w01.y, w23.x, w23.y, w45.x, w45.y, w67.x, w67.y};
            #pragma unroll
            for (int o = 0; o < 8; o++) {
                FMA2(acc[o][0], wv[o], A.u[0], acc[o][0]);
                FMA2(acc[o][1], wv[o], A.u[1], acc[o][1]);
                FMA2(acc[o][2], wv[o], B.u[0], acc[o][2]);
                FMA2(acc[o][3], wv[o], B.u[1], acc[o][3]);
            }
        }
        __syncthreads();
    }

    #pragma unroll
    for (int o = 0; o < 8; o++) {
        float* orow = g_rev + (ot + o)*HWSZ;
        #pragma unroll
        for (int pr = 0; pr < 4; pr++) {
            int p0 = ((pr >> 1) ? 128 : 0) + 4*lane + (pr & 1)*2;
            int py = p0 >> 4, px = p0 & 15;
            *(ull*)(orow + (ph + py)*WW + pw + px) = acc[o][pr];
        }
    }
}

// ---------------- fuse1: 1x1 conv + per-patch circular conv + add rev ----------------
// smem: E2p float[64][272] 69632 | Wp ull[64][64] 32768 | G float[64][64] 16384
#define F1_SMEM (69632 + 32768 + 16384)

__global__ void __launch_bounds__(256, 1) k_fuse1(const float* __restrict__ enc) {
    extern __shared__ char dsm[];
    float* E2p = (float*)dsm;                 // also EncS [j][272] during GEMM
    ull*   Wp  = (ull*)(dsm + 69632);
    float* G   = (float*)(dsm + 69632 + 32768);

    int tid = threadIdx.x;
    int lane = tid & 31;
    int ot = (tid >> 5) * 8;
    int ph = blockIdx.y * 16, pw = blockIdx.x * 16;

    // stage weights + G
    {
        const ulonglong2* wsrc = (const ulonglong2*)g_wpit2;
        ulonglong2* wdst = (ulonglong2*)Wp;
        #pragma unroll
        for (int i = 0; i < 8; i++) wdst[tid + i*256] = wsrc[tid + i*256];
        const float4* gsrc = (const float4*)g_gg;
        float4* gdst = (float4*)G;
        #pragma unroll
        for (int i = 0; i < 4; i++) gdst[tid + i*256] = gsrc[tid + i*256];
    }
    // stage EncS[j][p] from enc NCHW
    #pragma unroll
    for (int i = 0; i < 16; i++) {
        int f = i*256 + tid;
        int j = f >> 6, p4 = f & 63;
        int py = p4 >> 2, px4 = (p4 & 3) * 4;
        *(float4*)&E2p[j*272 + p4*4] =
            *(const float4*)(enc + j*HWSZ + (ph + py)*WW + pw + px4);
    }
    __syncthreads();

    // GEMM: e2[c][p] = sum_j Wpi[c][j] * enc[j][p]
    ull acc[8][4];
    #pragma unroll
    for (int o = 0; o < 8; o++)
        #pragma unroll
        for (int pr = 0; pr < 4; pr++) acc[o][pr] = 0ull;

    #pragma unroll 8
    for (int j = 0; j < 64; j++) {
        union { float4 f; ull u[2]; } A, B;
        A.f = *(const float4*)&E2p[j*272 + 4*lane];
        B.f = *(const float4*)&E2p[j*272 + 128 + 4*lane];
        const ulonglong2* wp = (const ulonglong2*)(Wp + j*64 + ot);
        ulonglong2 w01 = wp[0], w23 = wp[1], w45 = wp[2], w67 = wp[3];
        ull wv[8] = {w01.x, w01.y, w23.x, w23.y, w45.x, w45.y, w67.x, w67.y};
        #pragma unroll
        for (int o = 0; o < 8; o++) {
            FMA2(acc[o][0], wv[o], A.u[0], acc[o][0]);
            FMA2(acc[o][1], wv[o], A.u[1], acc[o][1]);
            FMA2(acc[o][2], wv[o], B.u[0], acc[o][2]);
            FMA2(acc[o][3], wv[o], B.u[1], acc[o][3]);
        }
    }
    __syncthreads();

    // write e2 into patch-major smem: E2p[c][patch*68 + q]
    #pragma unroll
    for (int o = 0; o < 8; o++)
        #pragma unroll
        for (int pr = 0; pr < 4; pr++) {
            int p0 = ((pr >> 1) ? 128 : 0) + 4*lane + (pr & 1)*2;
            int py = p0 >> 4, px = p0 & 15;
            int patch = ((py >> 3) << 1) | (px >> 3);
            int q = (py & 7)*8 + (px & 7);
            *(ull*)&E2p[(ot + o)*272 + patch*68 + q] = acc[o][pr];
        }
    __syncthreads();

    // circular conv per channel; thread owns pixel tid across all channels
    int py = tid >> 4, px = tid & 15;
    int patch = ((py >> 3) << 1) | (px >> 3);
    int lpy = py & 7, lpx = px & 7;
    unsigned int uidx[16];
    #pragma unroll
    for (int jj = 0; jj < 16; jj++) {
        unsigned int u = 0;
        #pragma unroll
        for (int b = 0; b < 4; b++) {
            int q = jj*4 + b;
            int v = (((lpy - (q >> 3)) & 7) << 3) | ((lpx - (q & 7)) & 7);
            u |= (unsigned int)v << (8*b);
        }
        uidx[jj] = u;
    }
    int gp0 = (ph + py)*WW + pw + px;
    for (int c = 0; c < 64; c++) {
        const float* gc = G + c*64;
        const float* ep = E2p + c*272 + patch*68;
        float s = 0.f;
        #pragma unroll
        for (int jj = 0; jj < 16; jj++) {
            float4 ev = *(const float4*)(ep + jj*4);
            unsigned int u = uidx[jj];
            s += ev.x * gc[u & 63];
            s += ev.y * gc[(u >> 8) & 63];
            s += ev.z * gc[(u >> 16) & 63];
            s += ev.w * gc[(u >> 24) & 63];
        }
        int gi = c*HWSZ + gp0;
        g_epre[gi] = s + g_rev[gi];
    }
}

// ---------------- fuse2: conv3x3 + concat-proj(128->128) + SimpleGate ----------------
// smem: Vsh float[64][260] 66560 | Wp ull[64][128] 65536
#define F2_SMEM (66560 + 65536)

__global__ void __launch_bounds__(256, 1) k_fuse2(const float* __restrict__ dec,
                                                  float* __restrict__ out) {
    extern __shared__ char dsm[];
    float* Vsh = (float*)dsm;
    ull*   Wp  = (ull*)(dsm + 66560);

    int tid = threadIdx.x;
    int lane = tid & 31;
    int ot = (tid >> 5) * 8;
    int ph = blockIdx.y * 16, pw = blockIdx.x * 16;
    int sy = tid >> 4, sx = tid & 15;    // staging pixel

    // ---- conv3x3 over 9 taps ----
    ull acc[8][4];
    #pragma unroll
    for (int o = 0; o < 8; o++)
        #pragma unroll
        for (int pr = 0; pr < 4; pr++) acc[o][pr] = 0ull;

    for (int k = 0; k < 9; k++) {
        int dy = k/3 - 1, dx = k%3 - 1;
        // stage weights into Wp[c][0..63]
        #pragma unroll
        for (int i = 0; i < 16; i++) {
            int f = i*256 + tid;
            int c = f >> 6, o = f & 63;
            Wp[c*128 + o] = g_wc2t2[k*4096 + f];
        }
        // stage V
        int h = ph + sy + dy, w = pw + sx + dx;
        bool ok = (h >= 0) && (h < HH) && (w >= 0) && (w < WW);
        const float* src = g_epre + h*WW + w;
        #pragma unroll
        for (int c = 0; c < 64; c++)
            Vsh[c*260 + tid] = ok ? src[c*HWSZ] : 0.f;
        __syncthreads();

        #pragma unroll 8
        for (int c = 0; c < 64; c++) {
            union { float4 f; ull u[2]; } A, B;
            A.f = *(const float4*)&Vsh[c*260 + 4*lane];
            B.f = *(const float4*)&Vsh[c*260 + 128 + 4*lane];
            const ulonglong2* wp = (const ulonglong2*)(Wp + c*128 + ot);
            ulonglong2 w01 = wp[0], w23 = wp[1], w45 = wp[2], w67 = wp[3];
            ull wv[8] = {w01.x, w01.y, w23.x, w23.y, w45.x, w45.y, w67.x, w67.y};
            #pragma unroll
            for (int o = 0; o < 8; o++) {
                FMA2(acc[o][0], wv[o], A.u[0], acc[o][0]);
                FMA2(acc[o][1], wv[o], A.u[1], acc[o][1]);
                FMA2(acc[o][2], wv[o], B.u[0], acc[o][2]);
                FMA2(acc[o][3], wv[o], B.u[1], acc[o][3]);
            }
        }
        __syncthreads();
    }

    // ---- write e3 into Vsh [c][p] ----
    #pragma unroll
    for (int o = 0; o < 8; o++)
        #pragma unroll
        for (int pr = 0; pr < 4; pr++) {
            int p0 = ((pr >> 1) ? 128 : 0) + 4*lane + (pr & 1)*2;
            *(ull*)&Vsh[(ot + o)*260 + p0] = acc[o][pr];
        }

    // ---- proj + gate: two source stages (e3, dec), dual accumulators ----
    ull a1[8][4], a2[8][4];
    #pragma unroll
    for (int o = 0; o < 8; o++)
        #pragma unroll
        for (int pr = 0; pr < 4; pr++) { a1[o][pr] = 0ull; a2[o][pr] = 0ull; }

    for (int s = 0; s < 2; s++) {
        // stage weights Wp[c][0..127] for this source stage
        #pragma unroll
        for (int i = 0; i < 32; i++) {
            int f = i*256 + tid;
            Wp[f] = g_wpot2[s*8192 + f];
        }
        if (s == 1) {
            // overwrite Vsh with dec tile (e3 GEMM already consumed via sync below)
            __syncthreads();
            const float* src = dec + (ph + sy)*WW + pw + sx;
            #pragma unroll
            for (int c = 0; c < 64; c++)
                Vsh[c*260 + tid] = src[c*HWSZ];
        }
        __syncthreads();

        #pragma unroll 4
        for (int c = 0; c < 64; c++) {
            union { float4 f; ull u[2]; } A, B;
            A.f = *(const float4*)&Vsh[c*260 + 4*lane];
            B.f = *(const float4*)&Vsh[c*260 + 128 + 4*lane];
            const ulonglong2* wp1 = (const ulonglong2*)(Wp + c*128 + ot);
            const ulonglong2* wp2 = (const ulonglong2*)(Wp + c*128 + 64 + ot);
            ulonglong2 u01 = wp1[0], u23 = wp1[1], u45 = wp1[2], u67 = wp1[3];
            ulonglong2 v01 = wp2[0], v23 = wp2[1], v45 = wp2[2], v67 = wp2[3];
            ull wv1[8] = {u01.x, u01.y, u23.x, u23.y, u45.x, u45.y, u67.x, u67.y};
            ull wv2[8] = {v01.x, v01.y, v23.x, v23.y, v45.x, v45.y, v67.x, v67.y};
            #pragma unroll
            for (int o = 0; o < 8; o++) {
                FMA2(a1[o][0], wv1[o], A.u[0], a1[o][0]);
                FMA2(a1[o][1], wv1[o], A.u[1], a1[o][1]);
                FMA2(a1[o][2], wv1[o], B.u[0], a1[o][2]);
                FMA2(a1[o][3], wv1[o], B.u[1], a1[o][3]);
                FMA2(a2[o][0], wv2[o], A.u[0], a2[o][0]);
                FMA2(a2[o][1], wv2[o], A.u[1], a2[o][1]);
                FMA2(a2[o][2], wv2[o], B.u[0], a2[o][2]);
                FMA2(a2[o][3], wv2[o], B.u[1], a2[o][3]);
            }
        }
        __syncthreads();
    }

    // ---- gate + write ----
    #pragma unroll
    for (int o = 0; o < 8; o++) {
        float* orow = out + (ot + o)*HWSZ;
        #pragma unroll
        for (int pr = 0; pr < 4; pr++) {
            int p0 = ((pr >> 1) ? 128 : 0) + 4*lane + (pr & 1)*2;
            int py = p0 >> 4, px = p0 & 15;
            float x1lo = __uint_as_float((unsigned int)(a1[o][pr] & 0xffffffffull));
            float x1hi = __uint_as_float((unsigned int)(a1[o][pr] >> 32));
            float x2lo = __uint_as_float((unsigned int)(a2[o][pr] & 0xffffffffull));
            float x2hi = __uint_as_float((unsigned int)(a2[o][pr] >> 32));
            float2 r = make_float2(x1lo*x2lo, x1hi*x2hi);
            *(float2*)(orow + (ph + py)*WW + pw + px) = r;
        }
    }
}

extern "C" void kernel_launch(void* const* d_in, const int* in_sizes, int n_in,
                              void* d_out, int out_size) {
    const float* enc  = (const float*)d_in[0];
    const float* dec  = (const float*)d_in[1];
    const float* ioff = (const float*)d_in[2];
    const float* iw   = (const float*)d_in[3];
    const float* wpi  = (const float*)d_in[4];
    const float* fftw = (const float*)d_in[5];
    const float* wpo  = (const float*)d_in[6];
    const float* wdef = (const float*)d_in[7];
    const float* wc1  = (const float*)d_in[8];
    const float* wc2  = (const float*)d_in[9];
    float* out = (float*)d_out;

    cudaFuncSetAttribute(k_deform, cudaFuncAttributeMaxDynamicSharedMemorySize, DEF_SMEM);
    cudaFuncSetAttribute(k_fuse1,  cudaFuncAttributeMaxDynamicSharedMemorySize, F1_SMEM);
    cudaFuncSetAttribute(k_fuse2,  cudaFuncAttributeMaxDynamicSharedMemorySize, F2_SMEM);

    k_prep_g   <<<64, 64>>>(fftw);
    k_prep_weff<<<(KTAPS*4096 + 255)/256, 256>>>(wc1, wdef);
    k_prep_tr  <<<144, 256>>>(wc2, wpo, wpi);
    k_transpose<<<576, 256>>>(enc);

    dim3 g12(12, 12);
    k_deform<<<g12, 256, DEF_SMEM>>>(ioff, iw);
    k_fuse1 <<<g12, 256, F1_SMEM>>>(enc);
    k_fuse2 <<<g12, 256, F2_SMEM>>>(dec, out);
}

// round 4
// speedup vs baseline: 1.4785x; 1.4785x over previous
#include <cuda_runtime.h>

#define HH 192
#define WW 192
#define HWSZ (192*192)
#define CC 64
#define KTAPS 49
#define PADK 3

#define FMA2(d,a,b,c) asm("fma.rn.f32x2 %0, %1, %2, %3;" : "=l"(d) : "l"(a), "l"(b), "l"(c))
#define MUL2(d,a,b)   asm("mul.rn.f32x2 %0, %1, %2;" : "=l"(d) : "l"(a), "l"(b))

typedef unsigned long long ull;

__device__ __forceinline__ ull packpair(float v) {
    unsigned int u = __float_as_uint(v);
    return ((ull)u << 32) | u;
}
__device__ __forceinline__ ull pack2(float lo, float hi) {
    return ((ull)__float_as_uint(hi) << 32) | __float_as_uint(lo);
}

// ---------------- scratch (no allocs allowed) ----------------
__device__ float g_rev [CC*HWSZ];
__device__ float g_fft [CC*HWSZ];        // fft-filter branch output (NCHW, no rev)
__device__ float g_e3  [CC*HWSZ];
__device__ float g_x1  [CC*HWSZ];
__device__ float g_encT[HWSZ*CC];        // NHWC
__device__ float g_e2pm[CC*64*576];      // [c][q=64][patch=576]
__device__ ull   g_weff2[KTAPS*64*64];   // [k][c][o] replicated pairs
__device__ ull   g_wc2t2[9*64*64];       // [k][c][o] pairs
__device__ ull   g_wph [2*128*64];       // [half][j128][o64] pairs
__device__ ull   g_wpit2[64*64];         // [j][c] pairs
__device__ float g_gg  [64*64];          // [c][a*8+d]

// ---------------- precompute: FFT filter -> circular conv kernel ----------------
__global__ void k_prep_g(const float* __restrict__ fw) {
    int c = blockIdx.x;           // 64
    int t = threadIdx.x;          // 64 : a*8+d
    int a = t >> 3, d = t & 7;
    const float ct[8] = {1.f, 0.70710678118654752f, 0.f, -0.70710678118654752f,
                        -1.f, -0.70710678118654752f, 0.f, 0.70710678118654752f};
    const float st[8] = {0.f, 0.70710678118654752f, 1.f, 0.70710678118654752f,
                         0.f, -0.70710678118654752f, -1.f, -0.70710678118654752f};
    const float* w = fw + c * 40; // [8][5]
    float re = 0.f;
    for (int u = 0; u < 8; u++) {
        float rp = w[u*5+0] + ((d & 1) ? -w[u*5+4] : w[u*5+4]);
        float ip = 0.f;
        #pragma unroll
        for (int v = 1; v <= 3; v++) {
            int vd = (v * d) & 7;
            rp += 2.f * w[u*5+v] * ct[vd];
            ip += 2.f * w[u*5+v] * st[vd];
        }
        int ua = (u * a) & 7;
        re += ct[ua] * rp - st[ua] * ip;
    }
    g_gg[c*64 + t] = re * (1.f/64.f);
}

// ---------------- precompute: fused deform weight, replicated pairs ----------------
__global__ void k_prep_weff(const float* __restrict__ wc1, const float* __restrict__ wd) {
    int idx = blockIdx.x * blockDim.x + threadIdx.x;   // k*4096 + c*64 + o
    if (idx >= KTAPS*64*64) return;
    int o = idx & 63, c = (idx >> 6) & 63, k = idx >> 12;
    float s = 0.f;
    for (int m = 0; m < 64; m++)
        s += wc1[o*64 + m] * wd[(m*64 + c)*49 + k];
    g_weff2[idx] = packpair(s);
}

// ---------------- precompute: weight transposes (pairs) ----------------
__global__ void k_prep_tr(const float* __restrict__ wc2, const float* __restrict__ wpo,
                          const float* __restrict__ wpi) {
    int idx = blockIdx.x * blockDim.x + threadIdx.x;
    if (idx < 9*4096) {                       // [k][c][o] <- wc2[o][c][k]
        int o = idx & 63, c = (idx >> 6) & 63, k = idx >> 12;
        g_wc2t2[idx] = packpair(wc2[(o*64 + c)*9 + k]);
    }
    if (idx < 2*128*64) {                     // [half][j][o] <- wpo[half*64+o][j]
        int half = idx >> 13, j = (idx >> 6) & 127, o = idx & 63;
        g_wph[idx] = packpair(wpo[(half*64 + o)*128 + j]);
    }
    if (idx < 4096) {                         // [j][c] <- wpi[c][j]
        int j = idx >> 6, c = idx & 63;
        g_wpit2[idx] = packpair(wpi[c*64 + j]);
    }
}

// ---------------- NCHW -> NHWC transpose of enc ----------------
__global__ void __launch_bounds__(256) k_transpose(const float* __restrict__ enc) {
    __shared__ float S[64][65];
    int tid = threadIdx.x;
    int p0 = blockIdx.x * 64;
    #pragma unroll
    for (int i = 0; i < 16; i++) {
        int e = i*256 + tid;
        int c = e >> 6, lp = e & 63;
        S[c][lp] = enc[c*HWSZ + p0 + lp];
    }
    __syncthreads();
    #pragma unroll
    for (int i = 0; i < 16; i++) {
        int e = i*256 + tid;           // e = lp*64 + c
        g_encT[p0*64 + e] = S[e & 63][e >> 6];
    }
}

// ---------------- deform conv (+ fused 1x1) : implicit GEMM, 16x16 tile ----------------
#define DEF_SMEM (66560 + 32768 + 4096 + 4096)

__global__ void __launch_bounds__(256, 1) k_deform(const float* __restrict__ off,
                                                   const float* __restrict__ msk) {
    extern __shared__ char dsm[];
    float* Vsh = (float*)dsm;
    ull*   Wsh2 = (ull*)(dsm + 66560);
    int*   sIdx = (int*)(dsm + 66560 + 32768);
    float* sWt  = (float*)(dsm + 66560 + 32768 + 4096);
    const float* encT = g_encT;

    int tid = threadIdx.x;
    int lane = tid & 31;
    int ot = (tid >> 5) * 8;           // warp-uniform o block
    int ph = blockIdx.y * 16, pw = blockIdx.x * 16;
    int ly = tid >> 4, lx = tid & 15;
    int h = ph + ly, w = pw + lx;
    int sp = h * WW + w;

    ull acc[8][4];
    #pragma unroll
    for (int o = 0; o < 8; o++)
        #pragma unroll
        for (int pr = 0; pr < 4; pr++) acc[o][pr] = 0ull;

    for (int k = 0; k < KTAPS; k++) {
        {
            const ulonglong2* wsrc = (const ulonglong2*)(g_weff2 + k*4096);
            ulonglong2* wdst = (ulonglong2*)Wsh2;
            #pragma unroll
            for (int i = 0; i < 8; i++) wdst[tid + i*256] = wsrc[tid + i*256];
        }
        {
            float dy = off[(2*k)*HWSZ + sp];
            float dx = off[(2*k+1)*HWSZ + sp];
            float m  = msk[k*HWSZ + sp];
            float yy = (float)(h - PADK + k/7) + dy;
            float xx = (float)(w - PADK + k%7) + dx;
            float y0f = floorf(yy), x0f = floorf(xx);
            float wy = yy - y0f, wx = xx - x0f;
            int y0 = (int)y0f, x0 = (int)x0f;
            int y1 = y0 + 1,   x1 = x0 + 1;
            bool vy0 = (y0 >= 0) && (y0 < HH), vy1 = (y1 >= 0) && (y1 < HH);
            bool vx0 = (x0 >= 0) && (x0 < WW), vx1 = (x1 >= 0) && (x1 < WW);
            int y0c = min(max(y0, 0), HH-1), y1c = min(max(y1, 0), HH-1);
            int x0c = min(max(x0, 0), WW-1), x1c = min(max(x1, 0), WW-1);
            sIdx[0*256 + tid] = (y0c*WW + x0c) * 64;
            sIdx[1*256 + tid] = (y0c*WW + x1c) * 64;
            sIdx[2*256 + tid] = (y1c*WW + x0c) * 64;
            sIdx[3*256 + tid] = (y1c*WW + x1c) * 64;
            sWt[0*256 + tid] = (vy0 && vx0) ? (1.f-wy)*(1.f-wx)*m : 0.f;
            sWt[1*256 + tid] = (vy0 && vx1) ? (1.f-wy)*wx*m       : 0.f;
            sWt[2*256 + tid] = (vy1 && vx0) ? wy*(1.f-wx)*m       : 0.f;
            sWt[3*256 + tid] = (vy1 && vx1) ? wy*wx*m             : 0.f;
        }
        __syncthreads();

        int c4 = tid & 15;
        #pragma unroll
        for (int it = 0; it < 4; it++) {
            int pq = (tid >> 4) + it * 16;
            int p0 = pq * 4;
            float4 r[4];
            #pragma unroll
            for (int pp = 0; pp < 4; pp++) {
                int p = p0 + pp;
                const float4 t0 = *(const float4*)(encT + sIdx[0*256 + p] + (c4 << 2));
                const float4 t1 = *(const float4*)(encT + sIdx[1*256 + p] + (c4 << 2));
                const float4 t2 = *(const float4*)(encT + sIdx[2*256 + p] + (c4 << 2));
                const float4 t3 = *(const float4*)(encT + sIdx[3*256 + p] + (c4 << 2));
                float w0 = sWt[0*256 + p], w1 = sWt[1*256 + p];
                float w2 = sWt[2*256 + p], w3 = sWt[3*256 + p];
                r[pp].x = w0*t0.x + w1*t1.x + w2*t2.x + w3*t3.x;
                r[pp].y = w0*t0.y + w1*t1.y + w2*t2.y + w3*t3.y;
                r[pp].z = w0*t0.z + w1*t1.z + w2*t2.z + w3*t3.z;
                r[pp].w = w0*t0.w + w1*t1.w + w2*t2.w + w3*t3.w;
            }
            float4 o0 = make_float4(r[0].x, r[1].x, r[2].x, r[3].x);
            float4 o1 = make_float4(r[0].y, r[1].y, r[2].y, r[3].y);
            float4 o2 = make_float4(r[0].z, r[1].z, r[2].z, r[3].z);
            float4 o3 = make_float4(r[0].w, r[1].w, r[2].w, r[3].w);
            *(float4*)&Vsh[(c4*4 + 0)*260 + p0] = o0;
            *(float4*)&Vsh[(c4*4 + 1)*260 + p0] = o1;
            *(float4*)&Vsh[(c4*4 + 2)*260 + p0] = o2;
            *(float4*)&Vsh[(c4*4 + 3)*260 + p0] = o3;
        }
        __syncthreads();

        #pragma unroll 8
        for (int c = 0; c < 64; c++) {
            union { float4 f; ull u[2]; } A, B;
            A.f = *(const float4*)&Vsh[c*260 + 4*lane];
            B.f = *(const float4*)&Vsh[c*260 + 128 + 4*lane];
            const ulonglong2* wp = (const ulonglong2*)(Wsh2 + c*64 + ot);
            ulonglong2 w01 = wp[0], w23 = wp[1], w45 = wp[2], w67 = wp[3];
            ull wv[8] = {w01.x, w01.y, w23.x, w23.y, w45.x, w45.y, w67.x, w67.y};
            #pragma unroll
            for (int o = 0; o < 8; o++) {
                FMA2(acc[o][0], wv[o], A.u[0], acc[o][0]);
                FMA2(acc[o][1], wv[o], A.u[1], acc[o][1]);
                FMA2(acc[o][2], wv[o], B.u[0], acc[o][2]);
                FMA2(acc[o][3], wv[o], B.u[1], acc[o][3]);
            }
        }
        __syncthreads();
    }

    #pragma unroll
    for (int o = 0; o < 8; o++) {
        float* orow = g_rev + (ot + o)*HWSZ;
        #pragma unroll
        for (int pr = 0; pr < 4; pr++) {
            int p0 = ((pr >> 1) ? 128 : 0) + 4*lane + (pr & 1)*2;
            int py = p0 >> 4, px = p0 & 15;
            *(ull*)(orow + (ph + py)*WW + pw + px) = acc[o][pr];
        }
    }
}

// ---------------- 1x1 conv on enc -> patch-major e2pm[c][q][patch] ----------------
// Each thread handles pixel pair (p, p+8): same q, adjacent patches -> ull store.
__global__ void __launch_bounds__(256) k_conv1x1pm(const float* __restrict__ enc) {
    __shared__ ull Wt[64*64];   // [j][c] pairs
    int tid = threadIdx.x;
    {
        const ulonglong2* src = (const ulonglong2*)g_wpit2;
        ulonglong2* dst = (ulonglong2*)Wt;
        #pragma unroll
        for (int i = 0; i < 8; i++) dst[tid + i*256] = src[tid + i*256];
    }
    __syncthreads();

    int base = blockIdx.x * 512;
    int p = base + (tid & 7) + (tid >> 3) * 16;   // p%16 in 0..7
    int p2 = p + 8;

    ull acc[64];
    #pragma unroll
    for (int c = 0; c < 64; c++) acc[c] = 0ull;

    for (int j = 0; j < 64; j++) {
        float a = enc[j*HWSZ + p];
        float b = enc[j*HWSZ + p2];
        ull v = pack2(a, b);
        const ulonglong2* wrow = (const ulonglong2*)(Wt + j*64);
        #pragma unroll
        for (int cc = 0; cc < 32; cc++) {
            ulonglong2 wv = wrow[cc];
            FMA2(acc[2*cc],   wv.x, v, acc[2*cc]);
            FMA2(acc[2*cc+1], wv.y, v, acc[2*cc+1]);
        }
    }

    int h = p / 192, w = p % 192;
    int q = (h & 7)*8 + (w & 7);
    int pat = (h >> 3)*24 + (w >> 3);   // even by construction
    #pragma unroll
    for (int c = 0; c < 64; c++)
        *(ull*)&g_e2pm[c*(64*576) + q*576 + pat] = acc[c];
}

// ---------------- per-patch circular conv as dense GEMM per channel ----------------
// block (c, pg): Y[64 p][192 patch] = Gmat_c[64][64] x E[64 q][192 patch]
// smem: Es float[64*196] 50176 | Wp ull[64*64] 32768
#define FFT_SMEM (50176 + 32768)

__global__ void __launch_bounds__(256, 1) k_fftgemm() {
    extern __shared__ char dsm[];
    float* Es = (float*)dsm;
    ull*   Wp = (ull*)(dsm + 50176);

    int tid = threadIdx.x;
    int lane = tid & 31;
    int c = blockIdx.x, pg = blockIdx.y;

    // stage E rows (192 floats each, stride 196)
    #pragma unroll
    for (int i = 0; i < 12; i++) {
        int f = i*256 + tid;            // 0..3071 float4 units
        int q = f / 48, r = f % 48;
        *(float4*)&Es[q*196 + r*4] =
            *(const float4*)&g_e2pm[c*(64*576) + q*576 + pg*192 + r*4];
    }
    // build Gmat pairs: Wp[q*64 + p]
    #pragma unroll
    for (int i = 0; i < 16; i++) {
        int f = i*256 + tid;
        int q = f >> 6, p = f & 63;
        int idx = (((p >> 3) - (q >> 3)) & 7)*8 + (((p & 7) - (q & 7)) & 7);
        Wp[f] = packpair(g_gg[c*64 + idx]);
    }
    __syncthreads();

    int pbase = (tid >> 5) * 8;
    ull acc[8][3];
    #pragma unroll
    for (int o = 0; o < 8; o++)
        #pragma unroll
        for (int g = 0; g < 3; g++) acc[o][g] = 0ull;

    #pragma unroll 8
    for (int q = 0; q < 64; q++) {
        ull A0 = *(const ull*)&Es[q*196 + 0*64 + 2*lane];
        ull A1 = *(const ull*)&Es[q*196 + 1*64 + 2*lane];
        ull A2 = *(const ull*)&Es[q*196 + 2*64 + 2*lane];
        const ulonglong2* wp = (const ulonglong2*)(Wp + q*64 + pbase);
        ulonglong2 w01 = wp[0], w23 = wp[1], w45 = wp[2], w67 = wp[3];
        ull wv[8] = {w01.x, w01.y, w23.x, w23.y, w45.x, w45.y, w67.x, w67.y};
        #pragma unroll
        for (int o = 0; o < 8; o++) {
            FMA2(acc[o][0], wv[o], A0, acc[o][0]);
            FMA2(acc[o][1], wv[o], A1, acc[o][1]);
            FMA2(acc[o][2], wv[o], A2, acc[o][2]);
        }
    }

    // scatter to NCHW g_fft
    float* dst = g_fft + c*HWSZ;
    #pragma unroll
    for (int o = 0; o < 8; o++) {
        int p = pbase + o;
        int py = p >> 3, px = p & 7;
        #pragma unroll
        for (int g = 0; g < 3; g++) {
            int pat = pg*192 + g*64 + 2*lane;
            float lo = __uint_as_float((unsigned int)(acc[o][g] & 0xffffffffull));
            float hi = __uint_as_float((unsigned int)(acc[o][g] >> 32));
            dst[((pat/24)*8 + py)*WW + (pat%24)*8 + px] = lo;
            pat++;
            dst[((pat/24)*8 + py)*WW + (pat%24)*8 + px] = hi;
        }
    }
}

// ---------------- 3x3 conv (pad 1), input = g_fft + g_rev, 16x16 f32x2 ----------------
// smem: Vsh float[64][260] 66560 | Wp ull[64*64] 32768
#define C3_SMEM (66560 + 32768)

__global__ void __launch_bounds__(256, 1) k_conv3() {
    extern __shared__ char dsm[];
    float* Vsh = (float*)dsm;
    ull*   Wp  = (ull*)(dsm + 66560);

    int tid = threadIdx.x;
    int lane = tid & 31;
    int ot = (tid >> 5) * 8;
    int ph = blockIdx.y * 16, pw = blockIdx.x * 16;
    int sy = tid >> 4, sx = tid & 15;

    ull acc[8][4];
    #pragma unroll
    for (int o = 0; o < 8; o++)
        #pragma unroll
        for (int pr = 0; pr < 4; pr++) acc[o][pr] = 0ull;

    for (int k = 0; k < 9; k++) {
        int dy = k/3 - 1, dx = k%3 - 1;
        {
            const ulonglong2* wsrc = (const ulonglong2*)(g_wc2t2 + k*4096);
            ulonglong2* wdst = (ulonglong2*)Wp;
            #pragma unroll
            for (int i = 0; i < 8; i++) wdst[tid + i*256] = wsrc[tid + i*256];
        }
        int h = ph + sy + dy, w = pw + sx + dx;
        bool ok = (h >= 0) && (h < HH) && (w >= 0) && (w < WW);
        int sp = h*WW + w;
        #pragma unroll
        for (int c = 0; c < 64; c++)
            Vsh[c*260 + tid] = ok ? (g_fft[c*HWSZ + sp] + g_rev[c*HWSZ + sp]) : 0.f;
        __syncthreads();

        #pragma unroll 8
        for (int c = 0; c < 64; c++) {
            union { float4 f; ull u[2]; } A, B;
            A.f = *(const float4*)&Vsh[c*260 + 4*lane];
            B.f = *(const float4*)&Vsh[c*260 + 128 + 4*lane];
            const ulonglong2* wp = (const ulonglong2*)(Wp + c*64 + ot);
            ulonglong2 w01 = wp[0], w23 = wp[1], w45 = wp[2], w67 = wp[3];
            ull wv[8] = {w01.x, w01.y, w23.x, w23.y, w45.x, w45.y, w67.x, w67.y};
            #pragma unroll
            for (int o = 0; o < 8; o++) {
                FMA2(acc[o][0], wv[o], A.u[0], acc[o][0]);
                FMA2(acc[o][1], wv[o], A.u[1], acc[o][1]);
                FMA2(acc[o][2], wv[o], B.u[0], acc[o][2]);
                FMA2(acc[o][3], wv[o], B.u[1], acc[o][3]);
            }
        }
        __syncthreads();
    }

    #pragma unroll
    for (int o = 0; o < 8; o++) {
        float* orow = g_e3 + (ot + o)*HWSZ;
        #pragma unroll
        for (int pr = 0; pr < 4; pr++) {
            int p0 = ((pr >> 1) ? 128 : 0) + 4*lane + (pr & 1)*2;
            int py = p0 >> 4, px = p0 & 15;
            *(ull*)(orow + (ph + py)*WW + pw + px) = acc[o][pr];
        }
    }
}

// ---------------- proj(128->64 per half) + gate; half0 -> g_x1, half1 -> out ----------------
// smem: Va 66560 | Vb 66560 | Wp ull[128*64] 65536
#define PJ_SMEM (66560 + 66560 + 65536)

__global__ void __launch_bounds__(256, 1) k_projhalf(const float* __restrict__ dec,
                                                     float* __restrict__ out, int half) {
    extern __shared__ char dsm[];
    float* Va = (float*)dsm;
    float* Vb = (float*)(dsm + 66560);
    ull*   Wp = (ull*)(dsm + 2*66560);

    int tid = threadIdx.x;
    int lane = tid & 31;
    int ot = (tid >> 5) * 8;
    int ph = blockIdx.y * 16, pw = blockIdx.x * 16;
    int sy = tid >> 4, sx = tid & 15;
    int sp = (ph + sy)*WW + pw + sx;

    {
        const ulonglong2* wsrc = (const ulonglong2*)(g_wph + half*8192);
        ulonglong2* wdst = (ulonglong2*)Wp;
        #pragma unroll
        for (int i = 0; i < 16; i++) wdst[tid + i*256] = wsrc[tid + i*256];
    }
    #pragma unroll
    for (int c = 0; c < 64; c++) {
        Va[c*260 + tid] = g_e3[c*HWSZ + sp];
        Vb[c*260 + tid] = dec[c*HWSZ + sp];
    }
    __syncthreads();

    ull acc[8][4];
    #pragma unroll
    for (int o = 0; o < 8; o++)
        #pragma unroll
        for (int pr = 0; pr < 4; pr++) acc[o][pr] = 0ull;

    #pragma unroll 4
    for (int c = 0; c < 64; c++) {
        union { float4 f; ull u[2]; } A, B;
        A.f = *(const float4*)&Va[c*260 + 4*lane];
        B.f = *(const float4*)&Va[c*260 + 128 + 4*lane];
        const ulonglong2* wp = (const ulonglong2*)(Wp + c*64 + ot);
        ulonglong2 w01 = wp[0], w23 = wp[1], w45 = wp[2], w67 = wp[3];
        ull wv[8] = {w01.x, w01.y, w23.x, w23.y, w45.x, w45.y, w67.x, w67.y};
        #pragma unroll
        for (int o = 0; o < 8; o++) {
            FMA2(acc[o][0], wv[o], A.u[0], acc[o][0]);
            FMA2(acc[o][1], wv[o], A.u[1], acc[o][1]);
            FMA2(acc[o][2], wv[o], B.u[0], acc[o][2]);
            FMA2(acc[o][3], wv[o], B.u[1], acc[o][3]);
        }
    }
    #pragma unroll 4
    for (int c = 0; c < 64; c++) {
        union { float4 f; ull u[2]; } A, B;
        A.f = *(const float4*)&Vb[c*260 + 4*lane];
        B.f = *(const float4*)&Vb[c*260 + 128 + 4*lane];
        const ulonglong2* wp = (const ulonglong2*)(Wp + (64 + c)*64 + ot);
        ulonglong2 w01 = wp[0], w23 = wp[1], w45 = wp[2], w67 = wp[3];
        ull wv[8] = {w01.x, w01.y, w23.x, w23.y, w45.x, w45.y, w67.x, w67.y};
        #pragma unroll
        for (int o = 0; o < 8; o++) {
            FMA2(acc[o][0], wv[o], A.u[0], acc[o][0]);
            FMA2(acc[o][1], wv[o], A.u[1], acc[o][1]);
            FMA2(acc[o][2], wv[o], B.u[0], acc[o][2]);
            FMA2(acc[o][3], wv[o], B.u[1], acc[o][3]);
        }
    }

    if (half == 0) {
        #pragma unroll
        for (int o = 0; o < 8; o++) {
            float* orow = g_x1 + (ot + o)*HWSZ;
            #pragma unroll
            for (int pr = 0; pr < 4; pr++) {
                int p0 = ((pr >> 1) ? 128 : 0) + 4*lane + (pr & 1)*2;
                int py = p0 >> 4, px = p0 & 15;
                *(ull*)(orow + (ph + py)*WW + pw + px) = acc[o][pr];
            }
        }
    } else {
        #pragma unroll
        for (int o = 0; o < 8; o++) {
            const float* xrow = g_x1 + (ot + o)*HWSZ;
            float* orow = out + (ot + o)*HWSZ;
            #pragma unroll
            for (int pr = 0; pr < 4; pr++) {
                int p0 = ((pr >> 1) ? 128 : 0) + 4*lane + (pr & 1)*2;
                int py = p0 >> 4, px = p0 & 15;
                int gi = (ph + py)*WW + pw + px;
                ull x1v = *(const ull*)(xrow + gi);
                ull r;
                MUL2(r, x1v, acc[o][pr]);
                *(ull*)(orow + gi) = r;
            }
        }
    }
}

extern "C" void kernel_launch(void* const* d_in, const int* in_sizes, int n_in,
                              void* d_out, int out_size) {
    const float* enc  = (const float*)d_in[0];
    const float* dec  = (const float*)d_in[1];
    const float* ioff = (const float*)d_in[2];
    const float* iw   = (const float*)d_in[3];
    const float* wpi  = (const float*)d_in[4];
    const float* fftw = (const float*)d_in[5];
    const float* wpo  = (const float*)d_in[6];
    const float* wdef = (const float*)d_in[7];
    const float* wc1  = (const float*)d_in[8];
    const float* wc2  = (const float*)d_in[9];
    float* out = (float*)d_out;

    cudaFuncSetAttribute(k_deform,  cudaFuncAttributeMaxDynamicSharedMemorySize, DEF_SMEM);
    cudaFuncSetAttribute(k_fftgemm, cudaFuncAttributeMaxDynamicSharedMemorySize, FFT_SMEM);
    cudaFuncSetAttribute(k_conv3,   cudaFuncAttributeMaxDynamicSharedMemorySize, C3_SMEM);
    cudaFuncSetAttribute(k_projhalf,cudaFuncAttributeMaxDynamicSharedMemorySize, PJ_SMEM);

    k_prep_g   <<<64, 64>>>(fftw);
    k_prep_weff<<<(KTAPS*4096 + 255)/256, 256>>>(wc1, wdef);
    k_prep_tr  <<<144, 256>>>(wc2, wpo, wpi);
    k_transpose<<<576, 256>>>(enc);

    dim3 g12(12, 12);
    dim3 gfft(64, 3);
    k_deform   <<<g12, 256, DEF_SMEM>>>(ioff, iw);
    k_conv1x1pm<<<72, 256>>>(enc);
    k_fftgemm  <<<gfft, 256, FFT_SMEM>>>();
    k_conv3    <<<g12, 256, C3_SMEM>>>();
    k_projhalf <<<g12, 256, PJ_SMEM>>>(dec, out, 0);
    k_projhalf <<<g12, 256, PJ_SMEM>>>(dec, out, 1);
}

// round 6
// speedup vs baseline: 1.9013x; 1.2859x over previous
#include <cuda_runtime.h>
#include <cuda_bf16.h>
#include <mma.h>
#include <cstdint>

using namespace nvcuda;

#define HH 192
#define WW 192
#define HWSZ (192*192)
#define CC 64
#define KTAPS 49
#define PADK 3

#define FMA2(d,a,b,c) asm("fma.rn.f32x2 %0, %1, %2, %3;" : "=l"(d) : "l"(a), "l"(b), "l"(c))
#define MUL2(d,a,b)   asm("mul.rn.f32x2 %0, %1, %2;" : "=l"(d) : "l"(a), "l"(b))

typedef unsigned long long ull;

__device__ __forceinline__ ull packpair(float v) {
    unsigned int u = __float_as_uint(v);
    return ((ull)u << 32) | u;
}
__device__ __forceinline__ ull pack2(float lo, float hi) {
    return ((ull)__float_as_uint(hi) << 32) | __float_as_uint(lo);
}

// ---------------- scratch (no allocs allowed) ----------------
__device__ float g_rev [CC*HWSZ];
__device__ float g_fft [CC*HWSZ];
__device__ float g_e3  [CC*HWSZ];
__device__ float g_x1  [CC*HWSZ];
__device__ float g_encT[HWSZ*CC];        // NHWC
__device__ float g_e2pm[CC*64*576];      // [c][q=64][patch=576]
__device__ __nv_bfloat16 g_wbh[KTAPS*64*64];  // [k][o][c] hi
__device__ __nv_bfloat16 g_wbl[KTAPS*64*64];  // [k][o][c] lo
__device__ ull   g_wc2t2[9*64*64];       // [k][c][o] pairs
__device__ ull   g_wph [2*128*64];       // [half][j128][o64] pairs
__device__ ull   g_wpit2[64*64];         // [j][c] pairs
__device__ float g_gg  [64*64];          // [c][a*8+d]

// ---------------- precompute: FFT filter -> circular conv kernel ----------------
__global__ void k_prep_g(const float* __restrict__ fw) {
    int c = blockIdx.x;
    int t = threadIdx.x;
    int a = t >> 3, d = t & 7;
    const float ct[8] = {1.f, 0.70710678118654752f, 0.f, -0.70710678118654752f,
                        -1.f, -0.70710678118654752f, 0.f, 0.70710678118654752f};
    const float st[8] = {0.f, 0.70710678118654752f, 1.f, 0.70710678118654752f,
                         0.f, -0.70710678118654752f, -1.f, -0.70710678118654752f};
    const float* w = fw + c * 40;
    float re = 0.f;
    for (int u = 0; u < 8; u++) {
        float rp = w[u*5+0] + ((d & 1) ? -w[u*5+4] : w[u*5+4]);
        float ip = 0.f;
        #pragma unroll
        for (int v = 1; v <= 3; v++) {
            int vd = (v * d) & 7;
            rp += 2.f * w[u*5+v] * ct[vd];
            ip += 2.f * w[u*5+v] * st[vd];
        }
        int ua = (u * a) & 7;
        re += ct[ua] * rp - st[ua] * ip;
    }
    g_gg[c*64 + t] = re * (1.f/64.f);
}

// ---------------- precompute: fused deform weight -> bf16 hi/lo [k][o][c] ----------------
__global__ void k_prep_wbf(const float* __restrict__ wc1, const float* __restrict__ wd) {
    int idx = blockIdx.x * blockDim.x + threadIdx.x;   // k*4096 + c*64 + o
    if (idx >= KTAPS*64*64) return;
    int o = idx & 63, c = (idx >> 6) & 63, k = idx >> 12;
    float s = 0.f;
    for (int m = 0; m < 64; m++)
        s += wc1[o*64 + m] * wd[(m*64 + c)*49 + k];
    __nv_bfloat16 hi = __float2bfloat16(s);
    float hv = __bfloat162float(hi);
    __nv_bfloat16 lo = __float2bfloat16(s - hv);
    g_wbh[k*4096 + o*64 + c] = hi;
    g_wbl[k*4096 + o*64 + c] = lo;
}

// ---------------- precompute: weight transposes (pairs) ----------------
__global__ void k_prep_tr(const float* __restrict__ wc2, const float* __restrict__ wpo,
                          const float* __restrict__ wpi) {
    int idx = blockIdx.x * blockDim.x + threadIdx.x;
    if (idx < 9*4096) {
        int o = idx & 63, c = (idx >> 6) & 63, k = idx >> 12;
        g_wc2t2[idx] = packpair(wc2[(o*64 + c)*9 + k]);
    }
    if (idx < 2*128*64) {
        int half = idx >> 13, j = (idx >> 6) & 127, o = idx & 63;
        g_wph[idx] = packpair(wpo[(half*64 + o)*128 + j]);
    }
    if (idx < 4096) {
        int j = idx >> 6, c = idx & 63;
        g_wpit2[idx] = packpair(wpi[c*64 + j]);
    }
}

// ---------------- NCHW -> NHWC transpose of enc ----------------
__global__ void __launch_bounds__(256) k_transpose(const float* __restrict__ enc) {
    __shared__ float S[64][65];
    int tid = threadIdx.x;
    int p0 = blockIdx.x * 64;
    #pragma unroll
    for (int i = 0; i < 16; i++) {
        int e = i*256 + tid;
        S[e >> 6][e & 63] = enc[(e >> 6)*HWSZ + p0 + (e & 63)];
    }
    __syncthreads();
    #pragma unroll
    for (int i = 0; i < 16; i++) {
        int e = i*256 + tid;
        g_encT[p0*64 + e] = S[e & 63][e >> 6];
    }
}

// ---------------- deform conv via WMMA bf16-split ----------------
// smem layout (bytes):
//   VHI  [256 px][72 bf16] stride 144B : 36864
//   VLO  36864..73728
//   WHI  [64 o][72 bf16]   stride 144B : 73728..82944
//   WLO  82944..92160
//   SIDX 92160..96256   (int[4][256])
//   SWT  96256..100352  (float[4][256])
// readout reuses VHI/VLO as float D[256][68]
#define DW_VHI  0
#define DW_VLO  36864
#define DW_WHI  73728
#define DW_WLO  82944
#define DW_SIDX 92160
#define DW_SWT  96256
#define DW_SMEM 100352

__global__ void __launch_bounds__(256, 1) k_deform_wmma(const float* __restrict__ off,
                                                        const float* __restrict__ msk) {
    extern __shared__ char dsm[];
    __nv_bfloat16* Vhi = (__nv_bfloat16*)(dsm + DW_VHI);
    __nv_bfloat16* Vlo = (__nv_bfloat16*)(dsm + DW_VLO);
    __nv_bfloat16* Whi = (__nv_bfloat16*)(dsm + DW_WHI);
    __nv_bfloat16* Wlo = (__nv_bfloat16*)(dsm + DW_WLO);
    int*   sIdx = (int*)(dsm + DW_SIDX);
    float* sWt  = (float*)(dsm + DW_SWT);
    const float* encT = g_encT;

    int tid = threadIdx.x;
    int wid = tid >> 5;
    int w32 = wid * 32;                 // this warp's pixel-row base
    int ph = blockIdx.y * 16, pw = blockIdx.x * 16;
    int ly = tid >> 4, lx = tid & 15;
    int h = ph + ly, w = pw + lx;
    int sp = h * WW + w;

    wmma::fragment<wmma::accumulator, 16, 16, 16, float> dfr[2][4];
    #pragma unroll
    for (int m = 0; m < 2; m++)
        #pragma unroll
        for (int n = 0; n < 4; n++) wmma::fill_fragment(dfr[m][n], 0.f);

    for (int k = 0; k < KTAPS; k++) {
        // ---- stage W hi/lo: [o][c] global -> [o][72] smem ----
        #pragma unroll
        for (int i = 0; i < 2; i++) {
            int f = i*256 + tid;          // 0..511 : row = f>>3, chunk = f&7
            int row = f >> 3, ch = f & 7;
            *(float4*)((char*)Whi + row*144 + ch*16) =
                *(const float4*)(g_wbh + k*4096 + row*64 + ch*8);
            *(float4*)((char*)Wlo + row*144 + ch*16) =
                *(const float4*)(g_wbl + k*4096 + row*64 + ch*8);
        }
        // ---- sampling params ----
        {
            float dy = off[(2*k)*HWSZ + sp];
            float dx = off[(2*k+1)*HWSZ + sp];
            float m  = msk[k*HWSZ + sp];
            float yy = (float)(h - PADK + k/7) + dy;
            float xx = (float)(w - PADK + k%7) + dx;
            float y0f = floorf(yy), x0f = floorf(xx);
            float wy = yy - y0f, wx = xx - x0f;
            int y0 = (int)y0f, x0 = (int)x0f;
            int y1 = y0 + 1,   x1 = x0 + 1;
            bool vy0 = (y0 >= 0) && (y0 < HH), vy1 = (y1 >= 0) && (y1 < HH);
            bool vx0 = (x0 >= 0) && (x0 < WW), vx1 = (x1 >= 0) && (x1 < WW);
            int y0c = min(max(y0, 0), HH-1), y1c = min(max(y1, 0), HH-1);
            int x0c = min(max(x0, 0), WW-1), x1c = min(max(x1, 0), WW-1);
            sIdx[0*256 + tid] = (y0c*WW + x0c) * 64;
            sIdx[1*256 + tid] = (y0c*WW + x1c) * 64;
            sIdx[2*256 + tid] = (y1c*WW + x0c) * 64;
            sIdx[3*256 + tid] = (y1c*WW + x1c) * 64;
            sWt[0*256 + tid] = (vy0 && vx0) ? (1.f-wy)*(1.f-wx)*m : 0.f;
            sWt[1*256 + tid] = (vy0 && vx1) ? (1.f-wy)*wx*m       : 0.f;
            sWt[2*256 + tid] = (vy1 && vx0) ? wy*(1.f-wx)*m       : 0.f;
            sWt[3*256 + tid] = (vy1 && vx1) ? wy*wx*m             : 0.f;
        }
        __syncthreads();

        // ---- gather: bilinear fp32, split bf16 hi/lo into V[p][72] ----
        int c4 = tid & 15;
        #pragma unroll
        for (int it = 0; it < 4; it++) {
            int pq = (tid >> 4) + it * 16;
            int p0 = pq * 4;
            #pragma unroll
            for (int pp = 0; pp < 4; pp++) {
                int p = p0 + pp;
                const float4 t0 = *(const float4*)(encT + sIdx[0*256 + p] + (c4 << 2));
                const float4 t1 = *(const float4*)(encT + sIdx[1*256 + p] + (c4 << 2));
                const float4 t2 = *(const float4*)(encT + sIdx[2*256 + p] + (c4 << 2));
                const float4 t3 = *(const float4*)(encT + sIdx[3*256 + p] + (c4 << 2));
                float w0 = sWt[0*256 + p], w1 = sWt[1*256 + p];
                float w2 = sWt[2*256 + p], w3 = sWt[3*256 + p];
                float v0 = w0*t0.x + w1*t1.x + w2*t2.x + w3*t3.x;
                float v1 = w0*t0.y + w1*t1.y + w2*t2.y + w3*t3.y;
                float v2 = w0*t0.z + w1*t1.z + w2*t2.z + w3*t3.z;
                float v3 = w0*t0.w + w1*t1.w + w2*t2.w + w3*t3.w;
                uint32_t h01, h23, l01, l23;
                asm("cvt.rn.bf16x2.f32 %0, %1, %2;" : "=r"(h01) : "f"(v1), "f"(v0));
                asm("cvt.rn.bf16x2.f32 %0, %1, %2;" : "=r"(h23) : "f"(v3), "f"(v2));
                float hv0 = __uint_as_float(h01 << 16);
                float hv1 = __uint_as_float(h01 & 0xffff0000u);
                float hv2 = __uint_as_float(h23 << 16);
                float hv3 = __uint_as_float(h23 & 0xffff0000u);
                asm("cvt.rn.bf16x2.f32 %0, %1, %2;" : "=r"(l01) : "f"(v1 - hv1), "f"(v0 - hv0));
                asm("cvt.rn.bf16x2.f32 %0, %1, %2;" : "=r"(l23) : "f"(v3 - hv3), "f"(v2 - hv2));
                *(uint2*)((char*)Vhi + p*144 + c4*8) = make_uint2(h01, h23);
                *(uint2*)((char*)Vlo + p*144 + c4*8) = make_uint2(l01, l23);
            }
        }
        __syncthreads();

        // ---- WMMA: D[p][o] += Vhi·Whi + Vlo·Whi + Vhi·Wlo ----
        #pragma unroll
        for (int kc = 0; kc < 4; kc++) {
            wmma::fragment<wmma::matrix_a, 16, 16, 16, __nv_bfloat16, wmma::row_major> ah[2], al[2];
            #pragma unroll
            for (int m = 0; m < 2; m++) {
                wmma::load_matrix_sync(ah[m], Vhi + (w32 + m*16)*72 + kc*16, 72);
                wmma::load_matrix_sync(al[m], Vlo + (w32 + m*16)*72 + kc*16, 72);
            }
            #pragma unroll
            for (int n = 0; n < 4; n++) {
                wmma::fragment<wmma::matrix_b, 16, 16, 16, __nv_bfloat16, wmma::col_major> bh, bl;
                wmma::load_matrix_sync(bh, Whi + (n*16)*72 + kc*16, 72);
                wmma::load_matrix_sync(bl, Wlo + (n*16)*72 + kc*16, 72);
                #pragma unroll
                for (int m = 0; m < 2; m++) {
                    wmma::mma_sync(dfr[m][n], ah[m], bh, dfr[m][n]);
                    wmma::mma_sync(dfr[m][n], al[m], bh, dfr[m][n]);
                    wmma::mma_sync(dfr[m][n], ah[m], bl, dfr[m][n]);
                }
            }
        }
        __syncthreads();
    }

    // ---- readout: frags -> smem D[256][68] -> g_rev NCHW ----
    float* Dsh = (float*)dsm;
    #pragma unroll
    for (int m = 0; m < 2; m++)
        #pragma unroll
        for (int n = 0; n < 4; n++)
            wmma::store_matrix_sync(Dsh + (w32 + m*16)*68 + n*16, dfr[m][n], 68,
                                    wmma::mem_row_major);
    __syncthreads();
    {
        int p = tid;
        int base = (ph + (p >> 4))*WW + pw + (p & 15);
        #pragma unroll
        for (int o = 0; o < 64; o++)
            g_rev[o*HWSZ + base] = Dsh[p*68 + o];
    }
}

// ---------------- 1x1 conv on enc -> patch-major e2pm[c][q][patch] ----------------
__global__ void __launch_bounds__(256) k_conv1x1pm(const float* __restrict__ enc) {
    __shared__ ull Wt[64*64];
    int tid = threadIdx.x;
    {
        const ulonglong2* src = (const ulonglong2*)g_wpit2;
        ulonglong2* dst = (ulonglong2*)Wt;
        #pragma unroll
        for (int i = 0; i < 8; i++) dst[tid + i*256] = src[tid + i*256];
    }
    __syncthreads();

    int base = blockIdx.x * 512;
    int p = base + (tid & 7) + (tid >> 3) * 16;
    int p2 = p + 8;

    ull acc[64];
    #pragma unroll
    for (int c = 0; c < 64; c++) acc[c] = 0ull;

    for (int j = 0; j < 64; j++) {
        ull v = pack2(enc[j*HWSZ + p], enc[j*HWSZ + p2]);
        const ulonglong2* wrow = (const ulonglong2*)(Wt + j*64);
        #pragma unroll
        for (int cc = 0; cc < 32; cc++) {
            ulonglong2 wv = wrow[cc];
            FMA2(acc[2*cc],   wv.x, v, acc[2*cc]);
            FMA2(acc[2*cc+1], wv.y, v, acc[2*cc+1]);
        }
    }

    int h = p / 192, w = p % 192;
    int q = (h & 7)*8 + (w & 7);
    int pat = (h >> 3)*24 + (w >> 3);
    #pragma unroll
    for (int c = 0; c < 64; c++)
        *(ull*)&g_e2pm[c*(64*576) + q*576 + pat] = acc[c];
}

// ---------------- per-patch circular conv as dense GEMM per channel ----------------
#define FFT_SMEM (50176 + 32768)

__global__ void __launch_bounds__(256, 1) k_fftgemm() {
    extern __shared__ char dsm[];
    float* Es = (float*)dsm;
    ull*   Wp = (ull*)(dsm + 50176);

    int tid = threadIdx.x;
    int lane = tid & 31;
    int c = blockIdx.x, pg = blockIdx.y;

    #pragma unroll
    for (int i = 0; i < 12; i++) {
        int f = i*256 + tid;
        int q = f / 48, r = f % 48;
        *(float4*)&Es[q*196 + r*4] =
            *(const float4*)&g_e2pm[c*(64*576) + q*576 + pg*192 + r*4];
    }
    #pragma unroll
    for (int i = 0; i < 16; i++) {
        int f = i*256 + tid;
        int q = f >> 6, p = f & 63;
        int idx = (((p >> 3) - (q >> 3)) & 7)*8 + (((p & 7) - (q & 7)) & 7);
        Wp[f] = packpair(g_gg[c*64 + idx]);
    }
    __syncthreads();

    int pbase = (tid >> 5) * 8;
    ull acc[8][3];
    #pragma unroll
    for (int o = 0; o < 8; o++)
        #pragma unroll
        for (int g = 0; g < 3; g++) acc[o][g] = 0ull;

    #pragma unroll 8
    for (int q = 0; q < 64; q++) {
        ull A0 = *(const ull*)&Es[q*196 + 0*64 + 2*lane];
        ull A1 = *(const ull*)&Es[q*196 + 1*64 + 2*lane];
        ull A2 = *(const ull*)&Es[q*196 + 2*64 + 2*lane];
        const ulonglong2* wp = (const ulonglong2*)(Wp + q*64 + pbase);
        ulonglong2 w01 = wp[0], w23 = wp[1], w45 = wp[2], w67 = wp[3];
        ull wv[8] = {w01.x, w01.y, w23.x, w23.y, w45.x, w45.y, w67.x, w67.y};
        #pragma unroll
        for (int o = 0; o < 8; o++) {
            FMA2(acc[o][0], wv[o], A0, acc[o][0]);
            FMA2(acc[o][1], wv[o], A1, acc[o][1]);
            FMA2(acc[o][2], wv[o], A2, acc[o][2]);
        }
    }

    float* dst = g_fft + c*HWSZ;
    #pragma unroll
    for (int o = 0; o < 8; o++) {
        int p = pbase + o;
        int py = p >> 3, px = p & 7;
        #pragma unroll
        for (int g = 0; g < 3; g++) {
            int pat = pg*192 + g*64 + 2*lane;
            float lo = __uint_as_float((unsigned int)(acc[o][g] & 0xffffffffull));
            float hi = __uint_as_float((unsigned int)(acc[o][g] >> 32));
            dst[((pat/24)*8 + py)*WW + (pat%24)*8 + px] = lo;
            pat++;
            dst[((pat/24)*8 + py)*WW + (pat%24)*8 + px] = hi;
        }
    }
}

// ---------------- 3x3 conv (pad 1), input = g_fft + g_rev ----------------
#define C3_SMEM (66560 + 32768)

__global__ void __launch_bounds__(256, 1) k_conv3() {
    extern __shared__ char dsm[];
    float* Vsh = (float*)dsm;
    ull*   Wp  = (ull*)(dsm + 66560);

    int tid = threadIdx.x;
    int lane = tid & 31;
    int ot = (tid >> 5) * 8;
    int ph = blockIdx.y * 16, pw = blockIdx.x * 16;
    int sy = tid >> 4, sx = tid & 15;

    ull acc[8][4];
    #pragma unroll
    for (int o = 0; o < 8; o++)
        #pragma unroll
        for (int pr = 0; pr < 4; pr++) acc[o][pr] = 0ull;

    for (int k = 0; k < 9; k++) {
        int dy = k/3 - 1, dx = k%3 - 1;
        {
            const ulonglong2* wsrc = (const ulonglong2*)(g_wc2t2 + k*4096);
            ulonglong2* wdst = (ulonglong2*)Wp;
            #pragma unroll
            for (int i = 0; i < 8; i++) wdst[tid + i*256] = wsrc[tid + i*256];
        }
        int h = ph + sy + dy, w = pw + sx + dx;
        bool ok = (h >= 0) && (h < HH) && (w >= 0) && (w < WW);
        int sp = h*WW + w;
        #pragma unroll
        for (int c = 0; c < 64; c++)
            Vsh[c*260 + tid] = ok ? (g_fft[c*HWSZ + sp] + g_rev[c*HWSZ + sp]) : 0.f;
        __syncthreads();

        #pragma unroll 8
        for (int c = 0; c < 64; c++) {
            union { float4 f; ull u[2]; } A, B;
            A.f = *(const float4*)&Vsh[c*260 + 4*lane];
            B.f = *(const float4*)&Vsh[c*260 + 128 + 4*lane];
            const ulonglong2* wp = (const ulonglong2*)(Wp + c*64 + ot);
            ulonglong2 w01 = wp[0], w23 = wp[1], w45 = wp[2], w67 = wp[3];
            ull wv[8] = {w01.x, w01.y, w23.x, w23.y, w45.x, w45.y, w67.x, w67.y};
            #pragma unroll
            for (int o = 0; o < 8; o++) {
                FMA2(acc[o][0], wv[o], A.u[0], acc[o][0]);
                FMA2(acc[o][1], wv[o], A.u[1], acc[o][1]);
                FMA2(acc[o][2], wv[o], B.u[0], acc[o][2]);
                FMA2(acc[o][3], wv[o], B.u[1], acc[o][3]);
            }
        }
        __syncthreads();
    }

    #pragma unroll
    for (int o = 0; o < 8; o++) {
        float* orow = g_e3 + (ot + o)*HWSZ;
        #pragma unroll
        for (int pr = 0; pr < 4; pr++) {
            int p0 = ((pr >> 1) ? 128 : 0) + 4*lane + (pr & 1)*2;
            int py = p0 >> 4, px = p0 & 15;
            *(ull*)(orow + (ph + py)*WW + pw + px) = acc[o][pr];
        }
    }
}

// ---------------- proj(128->64 per half) + gate ----------------
#define PJ_SMEM (66560 + 66560 + 65536)

__global__ void __launch_bounds__(256, 1) k_projhalf(const float* __restrict__ dec,
                                                     float* __restrict__ out, int half) {
    extern __shared__ char dsm[];
    float* Va = (float*)dsm;
    float* Vb = (float*)(dsm + 66560);
    ull*   Wp = (ull*)(dsm + 2*66560);

    int tid = threadIdx.x;
    int lane = tid & 31;
    int ot = (tid >> 5) * 8;
    int ph = blockIdx.y * 16, pw = blockIdx.x * 16;
    int sy = tid >> 4, sx = tid & 15;
    int sp = (ph + sy)*WW + pw + sx;

    {
        const ulonglong2* wsrc = (const ulonglong2*)(g_wph + half*8192);
        ulonglong2* wdst = (ulonglong2*)Wp;
        #pragma unroll
        for (int i = 0; i < 16; i++) wdst[tid + i*256] = wsrc[tid + i*256];
    }
    #pragma unroll
    for (int c = 0; c < 64; c++) {
        Va[c*260 + tid] = g_e3[c*HWSZ + sp];
        Vb[c*260 + tid] = dec[c*HWSZ + sp];
    }
    __syncthreads();

    ull acc[8][4];
    #pragma unroll
    for (int o = 0; o < 8; o++)
        #pragma unroll
        for (int pr = 0; pr < 4; pr++) acc[o][pr] = 0ull;

    #pragma unroll 4
    for (int c = 0; c < 64; c++) {
        union { float4 f; ull u[2]; } A, B;
        A.f = *(const float4*)&Va[c*260 + 4*lane];
        B.f = *(const float4*)&Va[c*260 + 128 + 4*lane];
        const ulonglong2* wp = (const ulonglong2*)(Wp + c*64 + ot);
        ulonglong2 w01 = wp[0], w23 = wp[1], w45 = wp[2], w67 = wp[3];
        ull wv[8] = {w01.x, w01.y, w23.x, w23.y, w45.x, w45.y, w67.x, w67.y};
        #pragma unroll
        for (int o = 0; o < 8; o++) {
            FMA2(acc[o][0], wv[o], A.u[0], acc[o][0]);
            FMA2(acc[o][1], wv[o], A.u[1], acc[o][1]);
            FMA2(acc[o][2], wv[o], B.u[0], acc[o][2]);
            FMA2(acc[o][3], wv[o], B.u[1], acc[o][3]);
        }
    }
    #pragma unroll 4
    for (int c = 0; c < 64; c++) {
        union { float4 f; ull u[2]; } A, B;
        A.f = *(const float4*)&Vb[c*260 + 4*lane];
        B.f = *(const float4*)&Vb[c*260 + 128 + 4*lane];
        const ulonglong2* wp = (const ulonglong2*)(Wp + (64 + c)*64 + ot);
        ulonglong2 w01 = wp[0], w23 = wp[1], w45 = wp[2], w67 = wp[3];
        ull wv[8] = {w01.x, w01.y, w23.x, w23.y, w45.x, w45.y, w67.x, w67.y};
        #pragma unroll
        for (int o = 0; o < 8; o++) {
            FMA2(acc[o][0], wv[o], A.u[0], acc[o][0]);
            FMA2(acc[o][1], wv[o], A.u[1], acc[o][1]);
            FMA2(acc[o][2], wv[o], B.u[0], acc[o][2]);
            FMA2(acc[o][3], wv[o], B.u[1], acc[o][3]);
        }
    }

    if (half == 0) {
        #pragma unroll
        for (int o = 0; o < 8; o++) {
            float* orow = g_x1 + (ot + o)*HWSZ;
            #pragma unroll
            for (int pr = 0; pr < 4; pr++) {
                int p0 = ((pr >> 1) ? 128 : 0) + 4*lane + (pr & 1)*2;
                int py = p0 >> 4, px = p0 & 15;
                *(ull*)(orow + (ph + py)*WW + pw + px) = acc[o][pr];
            }
        }
    } else {
        #pragma unroll
        for (int o = 0; o < 8; o++) {
            const float* xrow = g_x1 + (ot + o)*HWSZ;
            float* orow = out + (ot + o)*HWSZ;
            #pragma unroll
            for (int pr = 0; pr < 4; pr++) {
                int p0 = ((pr >> 1) ? 128 : 0) + 4*lane + (pr & 1)*2;
                int py = p0 >> 4, px = p0 & 15;
                int gi = (ph + py)*WW + pw + px;
                ull x1v = *(const ull*)(xrow + gi);
                ull r;
                MUL2(r, x1v, acc[o][pr]);
                *(ull*)(orow + gi) = r;
            }
        }
    }
}

extern "C" void kernel_launch(void* const* d_in, const int* in_sizes, int n_in,
                              void* d_out, int out_size) {
    const float* enc  = (const float*)d_in[0];
    const float* dec  = (const float*)d_in[1];
    const float* ioff = (const float*)d_in[2];
    const float* iw   = (const float*)d_in[3];
    const float* wpi  = (const float*)d_in[4];
    const float* fftw = (const float*)d_in[5];
    const float* wpo  = (const float*)d_in[6];
    const float* wdef = (const float*)d_in[7];
    const float* wc1  = (const float*)d_in[8];
    const float* wc2  = (const float*)d_in[9];
    float* out = (float*)d_out;

    cudaFuncSetAttribute(k_deform_wmma, cudaFuncAttributeMaxDynamicSharedMemorySize, DW_SMEM);
    cudaFuncSetAttribute(k_fftgemm,     cudaFuncAttributeMaxDynamicSharedMemorySize, FFT_SMEM);
    cudaFuncSetAttribute(k_conv3,       cudaFuncAttributeMaxDynamicSharedMemorySize, C3_SMEM);
    cudaFuncSetAttribute(k_projhalf,    cudaFuncAttributeMaxDynamicSharedMemorySize, PJ_SMEM);

    dim3 g12(12, 12);
    dim3 gfft(64, 3);

    k_transpose  <<<576, 256>>>(enc);
    k_prep_wbf   <<<(KTAPS*4096 + 255)/256, 256>>>(wc1, wdef);
    k_prep_g     <<<64, 64>>>(fftw);
    k_deform_wmma<<<g12, 256, DW_SMEM>>>(ioff, iw);
    k_prep_tr    <<<144, 256>>>(wc2, wpo, wpi);
    k_conv1x1pm  <<<72, 256>>>(enc);
    k_fftgemm    <<<gfft, 256, FFT_SMEM>>>();
    k_conv3      <<<g12, 256, C3_SMEM>>>();
    k_projhalf   <<<g12, 256, PJ_SMEM>>>(dec, out, 0);
    k_projhalf   <<<g12, 256, PJ_SMEM>>>(dec, out, 1);
}